// round 1
// baseline (speedup 1.0000x reference)
#include <cuda_runtime.h>

// Fixed circuit unitary (phases folded): final_j = sum_b (Wre[j][b] + i*Wim[j][b]) * r_b
__device__ float g_Wre[16][16];
__device__ float g_Wim[16][16];

// ---------------------------------------------------------------------------
// Prep kernel: simulate the weight-dependent part of the circuit on all 16
// basis columns (one column per thread, statevector fully in registers).
// Wire w maps to bit (3-w)  (axis w+1 of [B,2,2,2,2] is more significant).
// ---------------------------------------------------------------------------
__global__ void prep_kernel(const float* __restrict__ weights) {
    int col = threadIdx.x;
    if (col >= 16) return;

    float sre[16], sim_[16];
#pragma unroll
    for (int j = 0; j < 16; j++) { sre[j] = (j == col) ? 1.f : 0.f; sim_[j] = 0.f; }

#pragma unroll
    for (int l = 0; l < 2; l++) {
        // RX(weights[l][w]) on each wire
#pragma unroll
        for (int w = 0; w < 4; w++) {
            float th = weights[l * 4 + w] * 0.5f;
            float c, s;
            sincosf(th, &s, &c);
            const int bit = 8 >> w;
#pragma unroll
            for (int j = 0; j < 16; j++) {
                if (j & bit) continue;
                const int k = j | bit;
                float are = sre[j], aim = sim_[j];
                float bre = sre[k], bim = sim_[k];
                // new0 = c*a - i*s*b ; new1 = -i*s*a + c*b
                sre[j] = c * are + s * bim;
                sim_[j] = c * aim - s * bre;
                sre[k] = c * bre + s * aim;
                sim_[k] = c * bim - s * are;
            }
        }
        // ring of CNOTs: (0,1),(1,2),(2,3),(3,0)
#pragma unroll
        for (int w = 0; w < 4; w++) {
            const int cb = 8 >> w;
            const int tb = 8 >> ((w + 1) & 3);
#pragma unroll
            for (int j = 0; j < 16; j++) {
                if ((j & cb) && !(j & tb)) {
                    const int k = j | tb;
                    float tre = sre[j], tim = sim_[j];
                    sre[j] = sre[k]; sim_[j] = sim_[k];
                    sre[k] = tre;    sim_[k] = tim;
                }
            }
        }
    }

    // Fold embedding phase (-i)^popcount(col) into this column.
    const int pc = __popc(col) & 3;
#pragma unroll
    for (int j = 0; j < 16; j++) {
        float re = sre[j], im = sim_[j];
        float wre, wim;
        if (pc == 0)      { wre = re;   wim = im;  }
        else if (pc == 1) { wre = im;   wim = -re; }   // * (-i)
        else if (pc == 2) { wre = -re;  wim = -im; }   // * (-1)
        else              { wre = -im;  wim = re;  }   // * (+i)
        g_Wre[j][col] = wre;
        g_Wim[j][col] = wim;
    }
}

// ---------------------------------------------------------------------------
// Main kernel: one sample per thread.
//   r_b = prod_w (b_w ? sin(x_w/2) : cos(x_w/2))   (wire w -> bit 3-w)
//   final_j = W_j . r  (complex), p_j = |final_j|^2
//   out_w = sum_j p_j * (1 - 2*bit_{3-w}(j))
// ---------------------------------------------------------------------------
__global__ __launch_bounds__(256) void qenc_main_kernel(
    const float4* __restrict__ x4, float4* __restrict__ out4, int n)
{
    __shared__ float sWre[16][16];
    __shared__ float sWim[16][16];
    const int t = threadIdx.x;
    ((float*)sWre)[t] = ((const float*)g_Wre)[t];
    ((float*)sWim)[t] = ((const float*)g_Wim)[t];
    __syncthreads();

    const int i = blockIdx.x * 256 + t;
    if (i >= n) return;

    const float4 xv = x4[i];
    float c0, s0, c1, s1, c2, s2, c3, s3;
    __sincosf(0.5f * xv.x, &s0, &c0);
    __sincosf(0.5f * xv.y, &s1, &c1);
    __sincosf(0.5f * xv.z, &s2, &c2);
    __sincosf(0.5f * xv.w, &s3, &c3);

    // r[16]: wire0 -> bit3 ... wire3 -> bit0
    float r[16];
    {
        float p00 = c0 * c1, p01 = c0 * s1, p10 = s0 * c1, p11 = s0 * s1; // bits 3,2
        float q00 = c2 * c3, q01 = c2 * s3, q10 = s2 * c3, q11 = s2 * s3; // bits 1,0
        r[0]  = p00 * q00; r[1]  = p00 * q01; r[2]  = p00 * q10; r[3]  = p00 * q11;
        r[4]  = p01 * q00; r[5]  = p01 * q01; r[6]  = p01 * q10; r[7]  = p01 * q11;
        r[8]  = p10 * q00; r[9]  = p10 * q01; r[10] = p10 * q10; r[11] = p10 * q11;
        r[12] = p11 * q00; r[13] = p11 * q01; r[14] = p11 * q10; r[15] = p11 * q11;
    }

    float o0 = 0.f, o1 = 0.f, o2 = 0.f, o3 = 0.f;
#pragma unroll
    for (int j = 0; j < 16; j++) {
        float re = 0.f, im = 0.f;
#pragma unroll
        for (int b = 0; b < 16; b++) {
            re = fmaf(sWre[j][b], r[b], re);
            im = fmaf(sWim[j][b], r[b], im);
        }
        float p = fmaf(re, re, im * im);
        o0 += (j & 8) ? -p : p;   // wire 0 -> bit 3
        o1 += (j & 4) ? -p : p;   // wire 1 -> bit 2
        o2 += (j & 2) ? -p : p;   // wire 2 -> bit 1
        o3 += (j & 1) ? -p : p;   // wire 3 -> bit 0
    }

    out4[i] = make_float4(o0, o1, o2, o3);
}

extern "C" void kernel_launch(void* const* d_in, const int* in_sizes, int n_in,
                              void* d_out, int out_size) {
    const float* x = (const float*)d_in[0];        // [B, 4] float32
    const float* weights = (const float*)d_in[1];  // [2, 4] float32
    float* out = (float*)d_out;                    // [B, 4] float32

    const int n = in_sizes[0] / 4;   // B samples

    prep_kernel<<<1, 16>>>(weights);
    qenc_main_kernel<<<(n + 255) / 256, 256>>>(
        (const float4*)x, (float4*)out, n);
}

// round 2
// speedup vs baseline: 1.2464x; 1.2464x over previous
#include <cuda_runtime.h>

// C_w[10][10] bilinear forms, wires packed in pairs: [i][k][{w,w+1}]
__device__ __align__(16) float g_C01[10][10][2];
__device__ __align__(16) float g_C23[10][10][2];

// pair index tables: i -> (PA[i], PB[i]), PA <= PB
__device__ const int d_PA[10] = {0,0,0,0,1,1,1,2,2,3};
__device__ const int d_PB[10] = {0,1,2,3,1,2,3,2,3,3};

// ---------------------------------------------------------------------------
// Prep: 16 threads simulate the weight circuit columns (with (-i)^popcount
// embedding phase folded in), then 256 threads build the 4 bilinear forms.
// Wire w maps to bit (3-w) of the basis index.
// ---------------------------------------------------------------------------
__global__ void prep_kernel(const float* __restrict__ weights) {
    __shared__ float shWre[16][16];   // [j][col]
    __shared__ float shWim[16][16];
    const int tid = threadIdx.x;

    if (tid < 16) {
        const int col = tid;
        float sre[16], sim_[16];
#pragma unroll
        for (int j = 0; j < 16; j++) { sre[j] = (j == col) ? 1.f : 0.f; sim_[j] = 0.f; }

#pragma unroll
        for (int l = 0; l < 2; l++) {
#pragma unroll
            for (int w = 0; w < 4; w++) {
                float th = weights[l * 4 + w] * 0.5f;
                float c, s;
                sincosf(th, &s, &c);
                const int bit = 8 >> w;
#pragma unroll
                for (int j = 0; j < 16; j++) {
                    if (j & bit) continue;
                    const int k = j | bit;
                    float are = sre[j], aim = sim_[j];
                    float bre = sre[k], bim = sim_[k];
                    sre[j] = c * are + s * bim;
                    sim_[j] = c * aim - s * bre;
                    sre[k] = c * bre + s * aim;
                    sim_[k] = c * bim - s * are;
                }
            }
#pragma unroll
            for (int w = 0; w < 4; w++) {
                const int cb = 8 >> w;
                const int tb = 8 >> ((w + 1) & 3);
#pragma unroll
                for (int j = 0; j < 16; j++) {
                    if ((j & cb) && !(j & tb)) {
                        const int k = j | tb;
                        float tre = sre[j], tim = sim_[j];
                        sre[j] = sre[k]; sim_[j] = sim_[k];
                        sre[k] = tre;    sim_[k] = tim;
                    }
                }
            }
        }

        const int pc = __popc(col) & 3;
#pragma unroll
        for (int j = 0; j < 16; j++) {
            float re = sre[j], im = sim_[j];
            float wre, wim;
            if (pc == 0)      { wre = re;   wim = im;  }
            else if (pc == 1) { wre = im;   wim = -re; }
            else if (pc == 2) { wre = -re;  wim = -im; }
            else              { wre = -im;  wim = re;  }
            shWre[j][col] = wre;
            shWim[j][col] = wim;
        }
    }
    __syncthreads();

    // A_w[x][y] = sum_j s_w(j) (Wre[j][x]Wre[j][y] + Wim[j][x]Wim[j][y])
    // C_w[(a,a')][(c,c')] with symmetrization multiplicities folded in.
    for (int idx = tid; idx < 400; idx += blockDim.x) {
        const int w = idx / 100;
        const int rem = idx % 100;
        const int i = rem / 10;
        const int k = rem % 10;
        const int a  = d_PA[i], a2 = d_PB[i];
        const int c  = d_PA[k], c2 = d_PB[k];
        const int bitpos = 3 - w;

        const int x1 = a * 4 + c,  y1 = a2 * 4 + c2;
        float A1 = 0.f;
#pragma unroll
        for (int j = 0; j < 16; j++) {
            float sgn = ((j >> bitpos) & 1) ? -1.f : 1.f;
            A1 += sgn * (shWre[j][x1] * shWre[j][y1] + shWim[j][x1] * shWim[j][y1]);
        }
        float C;
        if (a != a2 && c != c2) {
            const int x2 = a * 4 + c2, y2 = a2 * 4 + c;
            float A2 = 0.f;
#pragma unroll
            for (int j = 0; j < 16; j++) {
                float sgn = ((j >> bitpos) & 1) ? -1.f : 1.f;
                A2 += sgn * (shWre[j][x2] * shWre[j][y2] + shWim[j][x2] * shWim[j][y2]);
            }
            C = 2.f * (A1 + A2);
        } else if (a != a2 || c != c2) {
            C = 2.f * A1;
        } else {
            C = A1;
        }

        if (w < 2) g_C01[i][k][w]     = C;
        else       g_C23[i][k][w - 2] = C;
    }
}

// ---------------------------------------------------------------------------
// Packed f32x2 helpers
// ---------------------------------------------------------------------------
__device__ __forceinline__ unsigned long long ffma2(
    unsigned long long a, unsigned long long b, unsigned long long c) {
    unsigned long long d;
    asm("fma.rn.f32x2 %0, %1, %2, %3;" : "=l"(d) : "l"(a), "l"(b), "l"(c));
    return d;
}
__device__ __forceinline__ unsigned long long pk(float x) {
    unsigned long long d;
    asm("mov.b64 %0, {%1, %1};" : "=l"(d) : "f"(x));
    return d;
}

// ---------------------------------------------------------------------------
// Main: one sample/thread.
//   p_a = (a&2 ? s0 : c0)*(a&1 ? s1 : c1),  q likewise with wires 2,3
//   out_w = Pu^T C_w Qu  (Pu/Qu = 10 unique outer-product entries)
// Wires (0,1) and (2,3) evaluated together via fma.rn.f32x2.
// ---------------------------------------------------------------------------
__global__ __launch_bounds__(256) void qenc_main_kernel(
    const float4* __restrict__ x4, float4* __restrict__ out4, int n)
{
    __shared__ __align__(16) float sC01[10][10][2];   // 800 B
    __shared__ __align__(16) float sC23[10][10][2];
    const int t = threadIdx.x;
    if (t < 50) {
        ((float4*)sC01)[t] = ((const float4*)g_C01)[t];
        ((float4*)sC23)[t] = ((const float4*)g_C23)[t];
    }
    __syncthreads();

    const int i0 = blockIdx.x * 256 + t;
    if (i0 >= n) return;

    const float4 xv = x4[i0];
    float c0, s0, c1, s1, c2, s2, c3, s3;
    __sincosf(0.5f * xv.x, &s0, &c0);
    __sincosf(0.5f * xv.y, &s1, &c1);
    __sincosf(0.5f * xv.z, &s2, &c2);
    __sincosf(0.5f * xv.w, &s3, &c3);

    float p[4], q[4];
    p[0] = c0 * c1; p[1] = c0 * s1; p[2] = s0 * c1; p[3] = s0 * s1;
    q[0] = c2 * c3; q[1] = c2 * s3; q[2] = s2 * c3; q[3] = s2 * s3;

    constexpr int PA[10] = {0,0,0,0,1,1,1,2,2,3};
    constexpr int PB[10] = {0,1,2,3,1,2,3,2,3,3};

    unsigned long long qp[10];
#pragma unroll
    for (int k = 0; k < 10; k++) qp[k] = pk(q[PA[k]] * q[PB[k]]);

    unsigned long long acc01 = 0ull, acc23 = 0ull;
#pragma unroll
    for (int i = 0; i < 10; i++) {
        const ulonglong2* r01 = (const ulonglong2*)(&sC01[i][0][0]);
        const ulonglong2* r23 = (const ulonglong2*)(&sC23[i][0][0]);
        unsigned long long t01 = 0ull, t23 = 0ull;
#pragma unroll
        for (int kk = 0; kk < 5; kk++) {
            ulonglong2 v1 = r01[kk];
            ulonglong2 v2 = r23[kk];
            t01 = ffma2(v1.x, qp[2 * kk],     t01);
            t01 = ffma2(v1.y, qp[2 * kk + 1], t01);
            t23 = ffma2(v2.x, qp[2 * kk],     t23);
            t23 = ffma2(v2.y, qp[2 * kk + 1], t23);
        }
        unsigned long long ppi = pk(p[PA[i]] * p[PB[i]]);
        acc01 = ffma2(t01, ppi, acc01);
        acc23 = ffma2(t23, ppi, acc23);
    }

    float o0, o1, o2, o3;
    asm("mov.b64 {%0, %1}, %2;" : "=f"(o0), "=f"(o1) : "l"(acc01));
    asm("mov.b64 {%0, %1}, %2;" : "=f"(o2), "=f"(o3) : "l"(acc23));

    out4[i0] = make_float4(o0, o1, o2, o3);
}

extern "C" void kernel_launch(void* const* d_in, const int* in_sizes, int n_in,
                              void* d_out, int out_size) {
    const float* x = (const float*)d_in[0];        // [B, 4] float32
    const float* weights = (const float*)d_in[1];  // [2, 4] float32
    float* out = (float*)d_out;                    // [B, 4] float32

    const int n = in_sizes[0] / 4;

    prep_kernel<<<1, 256>>>(weights);
    qenc_main_kernel<<<(n + 255) / 256, 256>>>(
        (const float4*)x, (float4*)out, n);
}

// round 3
// speedup vs baseline: 1.4091x; 1.1306x over previous
#include <cuda_runtime.h>

// C_w[10][10] bilinear forms, wires packed in pairs: [i][k][{w,w+1}]
__device__ __align__(16) float g_C01[10][10][2];
__device__ __align__(16) float g_C23[10][10][2];

__device__ const int d_PA[10] = {0,0,0,0,1,1,1,2,2,3};
__device__ const int d_PB[10] = {0,1,2,3,1,2,3,2,3,3};

// ---------------------------------------------------------------------------
// Prep: 16 threads simulate the weight circuit columns (with (-i)^popcount
// embedding phase folded in), then 256 threads build the 4 bilinear forms.
// ---------------------------------------------------------------------------
__global__ void prep_kernel(const float* __restrict__ weights) {
    __shared__ float shWre[16][16];   // [j][col]
    __shared__ float shWim[16][16];
    const int tid = threadIdx.x;

    if (tid < 16) {
        const int col = tid;
        float sre[16], sim_[16];
#pragma unroll
        for (int j = 0; j < 16; j++) { sre[j] = (j == col) ? 1.f : 0.f; sim_[j] = 0.f; }

#pragma unroll
        for (int l = 0; l < 2; l++) {
#pragma unroll
            for (int w = 0; w < 4; w++) {
                float th = weights[l * 4 + w] * 0.5f;
                float c, s;
                sincosf(th, &s, &c);
                const int bit = 8 >> w;
#pragma unroll
                for (int j = 0; j < 16; j++) {
                    if (j & bit) continue;
                    const int k = j | bit;
                    float are = sre[j], aim = sim_[j];
                    float bre = sre[k], bim = sim_[k];
                    sre[j] = c * are + s * bim;
                    sim_[j] = c * aim - s * bre;
                    sre[k] = c * bre + s * aim;
                    sim_[k] = c * bim - s * are;
                }
            }
#pragma unroll
            for (int w = 0; w < 4; w++) {
                const int cb = 8 >> w;
                const int tb = 8 >> ((w + 1) & 3);
#pragma unroll
                for (int j = 0; j < 16; j++) {
                    if ((j & cb) && !(j & tb)) {
                        const int k = j | tb;
                        float tre = sre[j], tim = sim_[j];
                        sre[j] = sre[k]; sim_[j] = sim_[k];
                        sre[k] = tre;    sim_[k] = tim;
                    }
                }
            }
        }

        const int pc = __popc(col) & 3;
#pragma unroll
        for (int j = 0; j < 16; j++) {
            float re = sre[j], im = sim_[j];
            float wre, wim;
            if (pc == 0)      { wre = re;   wim = im;  }
            else if (pc == 1) { wre = im;   wim = -re; }
            else if (pc == 2) { wre = -re;  wim = -im; }
            else              { wre = -im;  wim = re;  }
            shWre[j][col] = wre;
            shWim[j][col] = wim;
        }
    }
    __syncthreads();

    for (int idx = tid; idx < 400; idx += blockDim.x) {
        const int w = idx / 100;
        const int rem = idx % 100;
        const int i = rem / 10;
        const int k = rem % 10;
        const int a  = d_PA[i], a2 = d_PB[i];
        const int c  = d_PA[k], c2 = d_PB[k];
        const int bitpos = 3 - w;

        const int x1 = a * 4 + c,  y1 = a2 * 4 + c2;
        float A1 = 0.f;
#pragma unroll
        for (int j = 0; j < 16; j++) {
            float sgn = ((j >> bitpos) & 1) ? -1.f : 1.f;
            A1 += sgn * (shWre[j][x1] * shWre[j][y1] + shWim[j][x1] * shWim[j][y1]);
        }
        float C;
        if (a != a2 && c != c2) {
            const int x2 = a * 4 + c2, y2 = a2 * 4 + c;
            float A2 = 0.f;
#pragma unroll
            for (int j = 0; j < 16; j++) {
                float sgn = ((j >> bitpos) & 1) ? -1.f : 1.f;
                A2 += sgn * (shWre[j][x2] * shWre[j][y2] + shWim[j][x2] * shWim[j][y2]);
            }
            C = 2.f * (A1 + A2);
        } else if (a != a2 || c != c2) {
            C = 2.f * A1;
        } else {
            C = A1;
        }

        if (w < 2) g_C01[i][k][w]     = C;
        else       g_C23[i][k][w - 2] = C;
    }
}

// ---------------------------------------------------------------------------
// Packed f32x2 helpers
// ---------------------------------------------------------------------------
__device__ __forceinline__ unsigned long long ffma2(
    unsigned long long a, unsigned long long b, unsigned long long c) {
    unsigned long long d;
    asm("fma.rn.f32x2 %0, %1, %2, %3;" : "=l"(d) : "l"(a), "l"(b), "l"(c));
    return d;
}
__device__ __forceinline__ unsigned long long pk(float x) {
    unsigned long long d;
    asm("mov.b64 %0, {%1, %1};" : "=l"(d) : "f"(x));
    return d;
}

// ---------------------------------------------------------------------------
// Main: TWO samples per thread; shared-mem C tiles loaded once, applied to
// both samples' qp vectors. 4 independent FFMA2 chains per sample pair.
// ---------------------------------------------------------------------------
__global__ __launch_bounds__(256) void qenc_main_kernel(
    const float4* __restrict__ x4, float4* __restrict__ out4, int n)
{
    __shared__ __align__(16) float sC01[10][10][2];   // 800 B
    __shared__ __align__(16) float sC23[10][10][2];
    const int t = threadIdx.x;
    if (t < 50) {
        ((float4*)sC01)[t] = ((const float4*)g_C01)[t];
        ((float4*)sC23)[t] = ((const float4*)g_C23)[t];
    }
    __syncthreads();

    const int iA = blockIdx.x * 512 + t;
    const int iB = iA + 256;
    if (iA >= n) return;
    const bool hasB = (iB < n);

    const float4 xa = x4[iA];
    const float4 xb = hasB ? x4[iB] : xa;

    float pA[4], qA[4], pB[4], qB[4];
    {
        float c0, s0, c1, s1, c2, s2, c3, s3;
        __sincosf(0.5f * xa.x, &s0, &c0);
        __sincosf(0.5f * xa.y, &s1, &c1);
        __sincosf(0.5f * xa.z, &s2, &c2);
        __sincosf(0.5f * xa.w, &s3, &c3);
        pA[0] = c0 * c1; pA[1] = c0 * s1; pA[2] = s0 * c1; pA[3] = s0 * s1;
        qA[0] = c2 * c3; qA[1] = c2 * s3; qA[2] = s2 * c3; qA[3] = s2 * s3;
    }
    {
        float c0, s0, c1, s1, c2, s2, c3, s3;
        __sincosf(0.5f * xb.x, &s0, &c0);
        __sincosf(0.5f * xb.y, &s1, &c1);
        __sincosf(0.5f * xb.z, &s2, &c2);
        __sincosf(0.5f * xb.w, &s3, &c3);
        pB[0] = c0 * c1; pB[1] = c0 * s1; pB[2] = s0 * c1; pB[3] = s0 * s1;
        qB[0] = c2 * c3; qB[1] = c2 * s3; qB[2] = s2 * c3; qB[3] = s2 * s3;
    }

    constexpr int PA[10] = {0,0,0,0,1,1,1,2,2,3};
    constexpr int PB[10] = {0,1,2,3,1,2,3,2,3,3};

    unsigned long long qpA[10], qpB[10];
#pragma unroll
    for (int k = 0; k < 10; k++) {
        qpA[k] = pk(qA[PA[k]] * qA[PB[k]]);
        qpB[k] = pk(qB[PA[k]] * qB[PB[k]]);
    }

    unsigned long long accA01 = 0ull, accA23 = 0ull;
    unsigned long long accB01 = 0ull, accB23 = 0ull;
#pragma unroll
    for (int i = 0; i < 10; i++) {
        const ulonglong2* r01 = (const ulonglong2*)(&sC01[i][0][0]);
        const ulonglong2* r23 = (const ulonglong2*)(&sC23[i][0][0]);
        unsigned long long tA01 = 0ull, tA23 = 0ull;
        unsigned long long tB01 = 0ull, tB23 = 0ull;
#pragma unroll
        for (int kk = 0; kk < 5; kk++) {
            const ulonglong2 v1 = r01[kk];
            const ulonglong2 v2 = r23[kk];
            tA01 = ffma2(v1.x, qpA[2 * kk],     tA01);
            tA01 = ffma2(v1.y, qpA[2 * kk + 1], tA01);
            tA23 = ffma2(v2.x, qpA[2 * kk],     tA23);
            tA23 = ffma2(v2.y, qpA[2 * kk + 1], tA23);
            tB01 = ffma2(v1.x, qpB[2 * kk],     tB01);
            tB01 = ffma2(v1.y, qpB[2 * kk + 1], tB01);
            tB23 = ffma2(v2.x, qpB[2 * kk],     tB23);
            tB23 = ffma2(v2.y, qpB[2 * kk + 1], tB23);
        }
        const unsigned long long ppA = pk(pA[PA[i]] * pA[PB[i]]);
        const unsigned long long ppB = pk(pB[PA[i]] * pB[PB[i]]);
        accA01 = ffma2(tA01, ppA, accA01);
        accA23 = ffma2(tA23, ppA, accA23);
        accB01 = ffma2(tB01, ppB, accB01);
        accB23 = ffma2(tB23, ppB, accB23);
    }

    {
        float o0, o1, o2, o3;
        asm("mov.b64 {%0, %1}, %2;" : "=f"(o0), "=f"(o1) : "l"(accA01));
        asm("mov.b64 {%0, %1}, %2;" : "=f"(o2), "=f"(o3) : "l"(accA23));
        out4[iA] = make_float4(o0, o1, o2, o3);
    }
    if (hasB) {
        float o0, o1, o2, o3;
        asm("mov.b64 {%0, %1}, %2;" : "=f"(o0), "=f"(o1) : "l"(accB01));
        asm("mov.b64 {%0, %1}, %2;" : "=f"(o2), "=f"(o3) : "l"(accB23));
        out4[iB] = make_float4(o0, o1, o2, o3);
    }
}

extern "C" void kernel_launch(void* const* d_in, const int* in_sizes, int n_in,
                              void* d_out, int out_size) {
    const float* x = (const float*)d_in[0];        // [B, 4] float32
    const float* weights = (const float*)d_in[1];  // [2, 4] float32
    float* out = (float*)d_out;                    // [B, 4] float32

    const int n = in_sizes[0] / 4;
    const int nPairs = (n + 1) / 2;

    prep_kernel<<<1, 256>>>(weights);
    qenc_main_kernel<<<(nPairs + 255) / 256, 256>>>(
        (const float4*)x, (float4*)out, n);
}

// round 4
// speedup vs baseline: 1.6392x; 1.1633x over previous
#include <cuda_runtime.h>

// Packed multilinear tensors: out_w = sum T_w[a,b,c,d] v0_a v1_b v2_c v3_d,
// v_w = (1, cos x_w, sin x_w).  Rows i=a*3+b (9), cols k=c*3+d (9, padded to 10).
// g_T01 lanes = wires {0,1}; g_T23 lanes = wires {2,3}.
__device__ __align__(16) float g_T01[9][10][2];
__device__ __align__(16) float g_T23[9][10][2];

// ---------------------------------------------------------------------------
// Prep: 16 threads simulate weight-circuit columns (embedding phase folded),
// then build A_w = sum_j s_w(j) (Wre_j Wre_j^T + Wim_j Wim_j^T), then the
// collapsed tensor transform T_w[abcd] = (1/16) sum_x sgn(x&m1) A_w[x][x^m2].
// ---------------------------------------------------------------------------
__global__ void prep_kernel(const float* __restrict__ weights) {
    __shared__ float shWre[16][16];   // [j][col]
    __shared__ float shWim[16][16];
    __shared__ float sA[4][16][16];
    const int tid = threadIdx.x;

    if (tid < 16) {
        const int col = tid;
        float sre[16], sim_[16];
#pragma unroll
        for (int j = 0; j < 16; j++) { sre[j] = (j == col) ? 1.f : 0.f; sim_[j] = 0.f; }

#pragma unroll
        for (int l = 0; l < 2; l++) {
#pragma unroll
            for (int w = 0; w < 4; w++) {
                float th = weights[l * 4 + w] * 0.5f;
                float c, s;
                sincosf(th, &s, &c);
                const int bit = 8 >> w;
#pragma unroll
                for (int j = 0; j < 16; j++) {
                    if (j & bit) continue;
                    const int k = j | bit;
                    float are = sre[j], aim = sim_[j];
                    float bre = sre[k], bim = sim_[k];
                    sre[j] = c * are + s * bim;
                    sim_[j] = c * aim - s * bre;
                    sre[k] = c * bre + s * aim;
                    sim_[k] = c * bim - s * are;
                }
            }
#pragma unroll
            for (int w = 0; w < 4; w++) {
                const int cb = 8 >> w;
                const int tb = 8 >> ((w + 1) & 3);
#pragma unroll
                for (int j = 0; j < 16; j++) {
                    if ((j & cb) && !(j & tb)) {
                        const int k = j | tb;
                        float tre = sre[j], tim = sim_[j];
                        sre[j] = sre[k]; sim_[j] = sim_[k];
                        sre[k] = tre;    sim_[k] = tim;
                    }
                }
            }
        }
        const int pc = __popc(col) & 3;
#pragma unroll
        for (int j = 0; j < 16; j++) {
            float re = sre[j], im = sim_[j];
            float wre, wim;
            if (pc == 0)      { wre = re;   wim = im;  }
            else if (pc == 1) { wre = im;   wim = -re; }
            else if (pc == 2) { wre = -re;  wim = -im; }
            else              { wre = -im;  wim = re;  }
            shWre[j][col] = wre;
            shWim[j][col] = wim;
        }
    }
    __syncthreads();

    // A_w[x][y], 4*16*16 = 1024 entries
    for (int idx = tid; idx < 1024; idx += blockDim.x) {
        const int w = idx >> 8;
        const int x = (idx >> 4) & 15;
        const int y = idx & 15;
        const int bitpos = 3 - w;
        float a = 0.f;
#pragma unroll
        for (int j = 0; j < 16; j++) {
            float sgn = ((j >> bitpos) & 1) ? -1.f : 1.f;
            a += sgn * (shWre[j][x] * shWre[j][y] + shWim[j][x] * shWim[j][y]);
        }
        sA[w][x][y] = a;
    }
    __syncthreads();

    // T_w[abcd]: idx = (1,cos,sin) per wire; wire0->bit3 ... wire3->bit0.
    for (int idx = tid; idx < 324; idx += blockDim.x) {
        const int w = idx / 81;
        const int rem = idx % 81;
        const int a = rem / 27, b = (rem / 9) % 3, c = (rem / 3) % 3, d = rem % 3;
        int m1 = 0, m2 = 0;
        if (a == 1) m1 |= 8; else if (a == 2) m2 |= 8;
        if (b == 1) m1 |= 4; else if (b == 2) m2 |= 4;
        if (c == 1) m1 |= 2; else if (c == 2) m2 |= 2;
        if (d == 1) m1 |= 1; else if (d == 2) m2 |= 1;
        float sum = 0.f;
#pragma unroll
        for (int x = 0; x < 16; x++) {
            float sgn = (__popc(x & m1) & 1) ? -1.f : 1.f;
            sum += sgn * sA[w][x][x ^ m2];
        }
        const float T = sum * 0.0625f;
        const int i = a * 3 + b;
        const int k = c * 3 + d;
        if (w < 2) g_T01[i][k][w]     = T;
        else       g_T23[i][k][w - 2] = T;
    }
    // zero the padded column 9
    if (tid < 36) {
        const int i = tid / 4;
        const int r = tid % 4;
        if (r < 2) g_T01[i][9][r]     = 0.f;
        else       g_T23[i][9][r - 2] = 0.f;
    }
}

// ---------------------------------------------------------------------------
// Packed f32x2 helpers
// ---------------------------------------------------------------------------
__device__ __forceinline__ unsigned long long ffma2(
    unsigned long long a, unsigned long long b, unsigned long long c) {
    unsigned long long d;
    asm("fma.rn.f32x2 %0, %1, %2, %3;" : "=l"(d) : "l"(a), "l"(b), "l"(c));
    return d;
}
__device__ __forceinline__ unsigned long long pk(float x) {
    unsigned long long d;
    asm("mov.b64 %0, {%1, %1};" : "=l"(d) : "f"(x));
    return d;
}

// Per-sample packed trig state
struct Samp {
    unsigned long long c0, s0, vb1, vb2;  // vb: (c1, s1) splats
    unsigned long long c2, s2, c3, s3;
    unsigned long long U0, U1, U2;        // accumulators over 'a', per tensor handled twice
};

// ---------------------------------------------------------------------------
// Main: two samples per thread. Tensor contraction
//   out = ((T . v3) . v2) . v1 . v0  with v = (1, cos, sin), fully packed f32x2.
// 166 FFMA2 per sample for all four wires.
// ---------------------------------------------------------------------------
__global__ __launch_bounds__(128) void qenc_main_kernel(
    const float4* __restrict__ x4, float4* __restrict__ out4, int n)
{
    __shared__ __align__(16) float sT01[9][10][2];   // 720 B
    __shared__ __align__(16) float sT23[9][10][2];
    const int t = threadIdx.x;
    if (t < 90) {
        if (t < 45) ((float4*)sT01)[t]      = ((const float4*)g_T01)[t];
        else        ((float4*)sT23)[t - 45] = ((const float4*)g_T23)[t - 45];
    }
    __syncthreads();

    const int iA = blockIdx.x * 256 + t;
    const int iB = iA + 128;
    if (iA >= n) return;
    const bool hasB = (iB < n);

    const float4 xa = x4[iA];
    const float4 xb = hasB ? x4[iB] : xa;

    unsigned long long c0A, s0A, c1A, s1A, c2A, s2A, c3A, s3A;
    unsigned long long c0B, s0B, c1B, s1B, c2B, s2B, c3B, s3B;
    {
        float c, s;
        __sincosf(xa.x, &s, &c); c0A = pk(c); s0A = pk(s);
        __sincosf(xa.y, &s, &c); c1A = pk(c); s1A = pk(s);
        __sincosf(xa.z, &s, &c); c2A = pk(c); s2A = pk(s);
        __sincosf(xa.w, &s, &c); c3A = pk(c); s3A = pk(s);
        __sincosf(xb.x, &s, &c); c0B = pk(c); s0B = pk(s);
        __sincosf(xb.y, &s, &c); c1B = pk(c); s1B = pk(s);
        __sincosf(xb.z, &s, &c); c2B = pk(c); s2B = pk(s);
        __sincosf(xb.w, &s, &c); c3B = pk(c); s3B = pk(s);
    }
    const unsigned long long one = pk(1.0f);

    // accumulators over 'a' index: [tensor(01/23)][a] for each sample
    unsigned long long UA01[3] = {0ull, 0ull, 0ull};
    unsigned long long UA23[3] = {0ull, 0ull, 0ull};
    unsigned long long UB01[3] = {0ull, 0ull, 0ull};
    unsigned long long UB23[3] = {0ull, 0ull, 0ull};

#pragma unroll
    for (int i = 0; i < 9; i++) {
        const int a = i / 3;
        const int b = i % 3;
        const ulonglong2* r01 = (const ulonglong2*)(&sT01[i][0][0]);
        const ulonglong2* r23 = (const ulonglong2*)(&sT23[i][0][0]);
        const ulonglong2 p0 = r01[0], p1 = r01[1], p2 = r01[2], p3 = r01[3], p4 = r01[4];
        const ulonglong2 q0 = r23[0], q1 = r23[1], q2 = r23[2], q3 = r23[3], q4 = r23[4];
        // e0..e8 = p0.x p0.y p1.x p1.y p2.x p2.y p3.x p3.y p4.x

        const unsigned long long vbA = (b == 0) ? one : (b == 1) ? c1A : s1A;
        const unsigned long long vbB = (b == 0) ? one : (b == 1) ? c1B : s1B;

        // sample A, tensor 01
        {
            unsigned long long t0 = ffma2(p0.y, c3A, p0.x); t0 = ffma2(p1.x, s3A, t0);
            unsigned long long t1 = ffma2(p2.x, c3A, p1.y); t1 = ffma2(p2.y, s3A, t1);
            unsigned long long t2 = ffma2(p3.y, c3A, p3.x); t2 = ffma2(p4.x, s3A, t2);
            unsigned long long u  = ffma2(t1, c2A, t0); u = ffma2(t2, s2A, u);
            UA01[a] = ffma2(u, vbA, UA01[a]);
        }
        // sample A, tensor 23
        {
            unsigned long long t0 = ffma2(q0.y, c3A, q0.x); t0 = ffma2(q1.x, s3A, t0);
            unsigned long long t1 = ffma2(q2.x, c3A, q1.y); t1 = ffma2(q2.y, s3A, t1);
            unsigned long long t2 = ffma2(q3.y, c3A, q3.x); t2 = ffma2(q4.x, s3A, t2);
            unsigned long long u  = ffma2(t1, c2A, t0); u = ffma2(t2, s2A, u);
            UA23[a] = ffma2(u, vbA, UA23[a]);
        }
        // sample B, tensor 01
        {
            unsigned long long t0 = ffma2(p0.y, c3B, p0.x); t0 = ffma2(p1.x, s3B, t0);
            unsigned long long t1 = ffma2(p2.x, c3B, p1.y); t1 = ffma2(p2.y, s3B, t1);
            unsigned long long t2 = ffma2(p3.y, c3B, p3.x); t2 = ffma2(p4.x, s3B, t2);
            unsigned long long u  = ffma2(t1, c2B, t0); u = ffma2(t2, s2B, u);
            UB01[a] = ffma2(u, vbB, UB01[a]);
        }
        // sample B, tensor 23
        {
            unsigned long long t0 = ffma2(q0.y, c3B, q0.x); t0 = ffma2(q1.x, s3B, t0);
            unsigned long long t1 = ffma2(q2.x, c3B, q1.y); t1 = ffma2(q2.y, s3B, t1);
            unsigned long long t2 = ffma2(q3.y, c3B, q3.x); t2 = ffma2(q4.x, s3B, t2);
            unsigned long long u  = ffma2(t1, c2B, t0); u = ffma2(t2, s2B, u);
            UB23[a] = ffma2(u, vbB, UB23[a]);
        }
    }

    {
        unsigned long long acc01 = ffma2(UA01[1], c0A, UA01[0]); acc01 = ffma2(UA01[2], s0A, acc01);
        unsigned long long acc23 = ffma2(UA23[1], c0A, UA23[0]); acc23 = ffma2(UA23[2], s0A, acc23);
        float o0, o1, o2, o3;
        asm("mov.b64 {%0, %1}, %2;" : "=f"(o0), "=f"(o1) : "l"(acc01));
        asm("mov.b64 {%0, %1}, %2;" : "=f"(o2), "=f"(o3) : "l"(acc23));
        out4[iA] = make_float4(o0, o1, o2, o3);
    }
    if (hasB) {
        unsigned long long acc01 = ffma2(UB01[1], c0B, UB01[0]); acc01 = ffma2(UB01[2], s0B, acc01);
        unsigned long long acc23 = ffma2(UB23[1], c0B, UB23[0]); acc23 = ffma2(UB23[2], s0B, acc23);
        float o0, o1, o2, o3;
        asm("mov.b64 {%0, %1}, %2;" : "=f"(o0), "=f"(o1) : "l"(acc01));
        asm("mov.b64 {%0, %1}, %2;" : "=f"(o2), "=f"(o3) : "l"(acc23));
        out4[iB] = make_float4(o0, o1, o2, o3);
    }
}

extern "C" void kernel_launch(void* const* d_in, const int* in_sizes, int n_in,
                              void* d_out, int out_size) {
    const float* x = (const float*)d_in[0];        // [B, 4] float32
    const float* weights = (const float*)d_in[1];  // [2, 4] float32
    float* out = (float*)d_out;                    // [B, 4] float32

    const int n = in_sizes[0] / 4;
    const int nBlocks = (n + 255) / 256;   // 256 samples per 128-thread block

    prep_kernel<<<1, 512>>>(weights);
    qenc_main_kernel<<<nBlocks, 128>>>((const float4*)x, (float4*)out, n);
}

// round 5
// speedup vs baseline: 1.8011x; 1.0987x over previous
#include <cuda_runtime.h>

// Staging (device) and fast-path (constant) copies of the multilinear tensors:
//   out_w = sum T_w[a,b,c,d] v0_a v1_b v2_c v3_d,  v_w = (1, cos x_w, sin x_w)
// layout [t][i][k][lane]: t=0 -> wires{0,1}, t=1 -> wires{2,3}; i=a*3+b; k=c*3+d.
__device__    __align__(16) float g_T[2][9][10][2];
__constant__  __align__(16) float c_T[2][9][10][2];

// ---------------------------------------------------------------------------
// Prep: 16 threads simulate weight-circuit columns (embedding phase folded),
// build A_w = sum_j s_w(j)(Wre_j Wre_j^T + Wim_j Wim_j^T), then collapse:
// T_w[abcd] = (1/16) sum_x sgn(popc(x&m1)) A_w[x][x^m2].
// ---------------------------------------------------------------------------
__global__ void prep_kernel(const float* __restrict__ weights) {
    __shared__ float shWre[16][16];   // [j][col]
    __shared__ float shWim[16][16];
    __shared__ float sA[4][16][16];
    const int tid = threadIdx.x;

    if (tid < 16) {
        const int col = tid;
        float sre[16], sim_[16];
#pragma unroll
        for (int j = 0; j < 16; j++) { sre[j] = (j == col) ? 1.f : 0.f; sim_[j] = 0.f; }

#pragma unroll
        for (int l = 0; l < 2; l++) {
#pragma unroll
            for (int w = 0; w < 4; w++) {
                float th = weights[l * 4 + w] * 0.5f;
                float c, s;
                sincosf(th, &s, &c);
                const int bit = 8 >> w;
#pragma unroll
                for (int j = 0; j < 16; j++) {
                    if (j & bit) continue;
                    const int k = j | bit;
                    float are = sre[j], aim = sim_[j];
                    float bre = sre[k], bim = sim_[k];
                    sre[j] = c * are + s * bim;
                    sim_[j] = c * aim - s * bre;
                    sre[k] = c * bre + s * aim;
                    sim_[k] = c * bim - s * are;
                }
            }
#pragma unroll
            for (int w = 0; w < 4; w++) {
                const int cb = 8 >> w;
                const int tb = 8 >> ((w + 1) & 3);
#pragma unroll
                for (int j = 0; j < 16; j++) {
                    if ((j & cb) && !(j & tb)) {
                        const int k = j | tb;
                        float tre = sre[j], tim = sim_[j];
                        sre[j] = sre[k]; sim_[j] = sim_[k];
                        sre[k] = tre;    sim_[k] = tim;
                    }
                }
            }
        }
        const int pc = __popc(col) & 3;
#pragma unroll
        for (int j = 0; j < 16; j++) {
            float re = sre[j], im = sim_[j];
            float wre, wim;
            if (pc == 0)      { wre = re;   wim = im;  }
            else if (pc == 1) { wre = im;   wim = -re; }
            else if (pc == 2) { wre = -re;  wim = -im; }
            else              { wre = -im;  wim = re;  }
            shWre[j][col] = wre;
            shWim[j][col] = wim;
        }
    }
    __syncthreads();

    for (int idx = tid; idx < 1024; idx += blockDim.x) {
        const int w = idx >> 8;
        const int x = (idx >> 4) & 15;
        const int y = idx & 15;
        const int bitpos = 3 - w;
        float a = 0.f;
#pragma unroll
        for (int j = 0; j < 16; j++) {
            float sgn = ((j >> bitpos) & 1) ? -1.f : 1.f;
            a += sgn * (shWre[j][x] * shWre[j][y] + shWim[j][x] * shWim[j][y]);
        }
        sA[w][x][y] = a;
    }
    __syncthreads();

    for (int idx = tid; idx < 324; idx += blockDim.x) {
        const int w = idx / 81;
        const int rem = idx % 81;
        const int a = rem / 27, b = (rem / 9) % 3, c = (rem / 3) % 3, d = rem % 3;
        int m1 = 0, m2 = 0;
        if (a == 1) m1 |= 8; else if (a == 2) m2 |= 8;
        if (b == 1) m1 |= 4; else if (b == 2) m2 |= 4;
        if (c == 1) m1 |= 2; else if (c == 2) m2 |= 2;
        if (d == 1) m1 |= 1; else if (d == 2) m2 |= 1;
        float sum = 0.f;
#pragma unroll
        for (int x = 0; x < 16; x++) {
            float sgn = (__popc(x & m1) & 1) ? -1.f : 1.f;
            sum += sgn * sA[w][x][x ^ m2];
        }
        const float T = sum * 0.0625f;
        const int i = a * 3 + b;
        const int k = c * 3 + d;
        g_T[w >> 1][i][k][w & 1] = T;
    }
    if (tid < 36) {                       // zero padded column 9
        const int t9 = tid / 18;
        const int i9 = (tid / 2) % 9;
        g_T[t9][i9][9][tid & 1] = 0.f;
    }
}

// ---------------------------------------------------------------------------
// Packed f32x2 helpers
// ---------------------------------------------------------------------------
__device__ __forceinline__ unsigned long long ffma2(
    unsigned long long a, unsigned long long b, unsigned long long c) {
    unsigned long long d;
    asm("fma.rn.f32x2 %0, %1, %2, %3;" : "=l"(d) : "l"(a), "l"(b), "l"(c));
    return d;
}
__device__ __forceinline__ unsigned long long add2(
    unsigned long long a, unsigned long long b) {
    unsigned long long d;
    asm("add.rn.f32x2 %0, %1, %2;" : "=l"(d) : "l"(a), "l"(b));
    return d;
}
__device__ __forceinline__ unsigned long long pk(float x) {
    unsigned long long d;
    asm("mov.b64 %0, {%1, %1};" : "=l"(d) : "f"(x));
    return d;
}

// constant-bank 64-bit fetch with compile-time offsets -> LDCU (uniform port)
__device__ __forceinline__ unsigned long long ct(int t, int i, int k) {
    return *reinterpret_cast<const unsigned long long*>(&c_T[t][i][k][0]);
}

// ---------------------------------------------------------------------------
// Main: two samples/thread. Tensor contraction, T from constant memory.
// ---------------------------------------------------------------------------
__global__ __launch_bounds__(128) void qenc_main_kernel(
    const float4* __restrict__ x4, float4* __restrict__ out4, int n)
{
    const int t = threadIdx.x;
    const int iA = blockIdx.x * 256 + t;
    const int iB = iA + 128;
    if (iA >= n) return;
    const bool hasB = (iB < n);

    const float4 xa = x4[iA];
    const float4 xb = hasB ? x4[iB] : xa;

    unsigned long long c0A, s0A, c1A, s1A, c2A, s2A, c3A, s3A;
    unsigned long long c0B, s0B, c1B, s1B, c2B, s2B, c3B, s3B;
    {
        float c, s;
        __sincosf(xa.x, &s, &c); c0A = pk(c); s0A = pk(s);
        __sincosf(xa.y, &s, &c); c1A = pk(c); s1A = pk(s);
        __sincosf(xa.z, &s, &c); c2A = pk(c); s2A = pk(s);
        __sincosf(xa.w, &s, &c); c3A = pk(c); s3A = pk(s);
        __sincosf(xb.x, &s, &c); c0B = pk(c); s0B = pk(s);
        __sincosf(xb.y, &s, &c); c1B = pk(c); s1B = pk(s);
        __sincosf(xb.z, &s, &c); c2B = pk(c); s2B = pk(s);
        __sincosf(xb.w, &s, &c); c3B = pk(c); s3B = pk(s);
    }

    // accumulators over 'a': U[a] built as u(a,0) + u(a,1)*c1 + u(a,2)*s1
    unsigned long long UA01[3], UA23[3], UB01[3], UB23[3];

#pragma unroll
    for (int a = 0; a < 3; a++) {
#pragma unroll
        for (int b = 0; b < 3; b++) {
            const int i = a * 3 + b;
            const unsigned long long e0 = ct(0, i, 0), e1 = ct(0, i, 1), e2 = ct(0, i, 2);
            const unsigned long long e3 = ct(0, i, 3), e4 = ct(0, i, 4), e5 = ct(0, i, 5);
            const unsigned long long e6 = ct(0, i, 6), e7 = ct(0, i, 7), e8 = ct(0, i, 8);
            const unsigned long long f0 = ct(1, i, 0), f1 = ct(1, i, 1), f2 = ct(1, i, 2);
            const unsigned long long f3 = ct(1, i, 3), f4 = ct(1, i, 4), f5 = ct(1, i, 5);
            const unsigned long long f6 = ct(1, i, 6), f7 = ct(1, i, 7), f8 = ct(1, i, 8);

            unsigned long long uA01, uA23, uB01, uB23;
            {
                unsigned long long t0 = ffma2(e1, c3A, e0); t0 = ffma2(e2, s3A, t0);
                unsigned long long t1 = ffma2(e4, c3A, e3); t1 = ffma2(e5, s3A, t1);
                unsigned long long t2 = ffma2(e7, c3A, e6); t2 = ffma2(e8, s3A, t2);
                uA01 = ffma2(t1, c2A, t0); uA01 = ffma2(t2, s2A, uA01);
            }
            {
                unsigned long long t0 = ffma2(f1, c3A, f0); t0 = ffma2(f2, s3A, t0);
                unsigned long long t1 = ffma2(f4, c3A, f3); t1 = ffma2(f5, s3A, t1);
                unsigned long long t2 = ffma2(f7, c3A, f6); t2 = ffma2(f8, s3A, t2);
                uA23 = ffma2(t1, c2A, t0); uA23 = ffma2(t2, s2A, uA23);
            }
            {
                unsigned long long t0 = ffma2(e1, c3B, e0); t0 = ffma2(e2, s3B, t0);
                unsigned long long t1 = ffma2(e4, c3B, e3); t1 = ffma2(e5, s3B, t1);
                unsigned long long t2 = ffma2(e7, c3B, e6); t2 = ffma2(e8, s3B, t2);
                uB01 = ffma2(t1, c2B, t0); uB01 = ffma2(t2, s2B, uB01);
            }
            {
                unsigned long long t0 = ffma2(f1, c3B, f0); t0 = ffma2(f2, s3B, t0);
                unsigned long long t1 = ffma2(f4, c3B, f3); t1 = ffma2(f5, s3B, t1);
                unsigned long long t2 = ffma2(f7, c3B, f6); t2 = ffma2(f8, s3B, t2);
                uB23 = ffma2(t1, c2B, t0); uB23 = ffma2(t2, s2B, uB23);
            }

            if (b == 0) { UA01[a] = uA01; UA23[a] = uA23; UB01[a] = uB01; UB23[a] = uB23; }
            else {
                const unsigned long long vbA = (b == 1) ? c1A : s1A;
                const unsigned long long vbB = (b == 1) ? c1B : s1B;
                UA01[a] = ffma2(uA01, vbA, UA01[a]);
                UA23[a] = ffma2(uA23, vbA, UA23[a]);
                UB01[a] = ffma2(uB01, vbB, UB01[a]);
                UB23[a] = ffma2(uB23, vbB, UB23[a]);
            }
        }
    }

    {
        unsigned long long acc01 = ffma2(UA01[1], c0A, UA01[0]); acc01 = ffma2(UA01[2], s0A, acc01);
        unsigned long long acc23 = ffma2(UA23[1], c0A, UA23[0]); acc23 = ffma2(UA23[2], s0A, acc23);
        float o0, o1, o2, o3;
        asm("mov.b64 {%0, %1}, %2;" : "=f"(o0), "=f"(o1) : "l"(acc01));
        asm("mov.b64 {%0, %1}, %2;" : "=f"(o2), "=f"(o3) : "l"(acc23));
        out4[iA] = make_float4(o0, o1, o2, o3);
    }
    if (hasB) {
        unsigned long long acc01 = ffma2(UB01[1], c0B, UB01[0]); acc01 = ffma2(UB01[2], s0B, acc01);
        unsigned long long acc23 = ffma2(UB23[1], c0B, UB23[0]); acc23 = ffma2(UB23[2], s0B, acc23);
        float o0, o1, o2, o3;
        asm("mov.b64 {%0, %1}, %2;" : "=f"(o0), "=f"(o1) : "l"(acc01));
        asm("mov.b64 {%0, %1}, %2;" : "=f"(o2), "=f"(o3) : "l"(acc23));
        out4[iB] = make_float4(o0, o1, o2, o3);
    }
}

extern "C" void kernel_launch(void* const* d_in, const int* in_sizes, int n_in,
                              void* d_out, int out_size) {
    const float* x = (const float*)d_in[0];        // [B, 4] float32
    const float* weights = (const float*)d_in[1];  // [2, 4] float32
    float* out = (float*)d_out;                    // [B, 4] float32

    const int n = in_sizes[0] / 4;
    const int nBlocks = (n + 255) / 256;   // 256 samples per 128-thread block

    void* cdst = nullptr;
    void* gsrc = nullptr;
    cudaGetSymbolAddress(&cdst, c_T);
    cudaGetSymbolAddress(&gsrc, g_T);

    prep_kernel<<<1, 256>>>(weights);
    cudaMemcpyAsync(cdst, gsrc, sizeof(float) * 2 * 9 * 10 * 2,
                    cudaMemcpyDeviceToDevice);
    qenc_main_kernel<<<nBlocks, 128>>>((const float4*)x, (float4*)out, n);
}

// round 6
// speedup vs baseline: 2.4573x; 1.3643x over previous
#include <cuda_runtime.h>

// 24 sparse tensor params:
//  [0..7]  P0: out0 = ((P0[0]c3+P0[1]s3)c1+(P0[2]c3+P0[3]s3)s1)c0 + ((P0[4]c3+P0[5]s3)c1+(P0[6]c3+P0[7]s3)s1)s0
//  [8..15] P1: same with (c2,s2) middle: out1
//  [16..19]P2: out2 = (P2[0]c3+P2[1]s3)c1 + (P2[2]c3+P2[3]s3)s1
//  [20..23]P3: out3 = (P3[0]c2+P3[1]s2)c0 + (P3[2]c2+P3[3]s2)s0
__device__   __align__(16) float g_P[24];
__constant__ __align__(16) float c_P[24];

// ---------------------------------------------------------------------------
// Prep: simulate weight circuit -> A_w -> multilinear tensor T (validated
// path from prior rounds), then extract the 24 structurally-nonzero entries.
// T index: a->wire0(bit3), b->wire1, c->wire2, d->wire3; 0=const,1=cos,2=sin.
// ---------------------------------------------------------------------------
__global__ void prep_kernel(const float* __restrict__ weights) {
    __shared__ float shWre[16][16];   // [j][col]
    __shared__ float shWim[16][16];
    __shared__ float sA[4][16][16];
    __shared__ float sT[4][9][9];     // [w][i=a*3+b][k=c*3+d]
    const int tid = threadIdx.x;

    if (tid < 16) {
        const int col = tid;
        float sre[16], sim_[16];
#pragma unroll
        for (int j = 0; j < 16; j++) { sre[j] = (j == col) ? 1.f : 0.f; sim_[j] = 0.f; }

#pragma unroll
        for (int l = 0; l < 2; l++) {
#pragma unroll
            for (int w = 0; w < 4; w++) {
                float th = weights[l * 4 + w] * 0.5f;
                float c, s;
                sincosf(th, &s, &c);
                const int bit = 8 >> w;
#pragma unroll
                for (int j = 0; j < 16; j++) {
                    if (j & bit) continue;
                    const int k = j | bit;
                    float are = sre[j], aim = sim_[j];
                    float bre = sre[k], bim = sim_[k];
                    sre[j] = c * are + s * bim;
                    sim_[j] = c * aim - s * bre;
                    sre[k] = c * bre + s * aim;
                    sim_[k] = c * bim - s * are;
                }
            }
#pragma unroll
            for (int w = 0; w < 4; w++) {
                const int cb = 8 >> w;
                const int tb = 8 >> ((w + 1) & 3);
#pragma unroll
                for (int j = 0; j < 16; j++) {
                    if ((j & cb) && !(j & tb)) {
                        const int k = j | tb;
                        float tre = sre[j], tim = sim_[j];
                        sre[j] = sre[k]; sim_[j] = sim_[k];
                        sre[k] = tre;    sim_[k] = tim;
                    }
                }
            }
        }
        const int pc = __popc(col) & 3;
#pragma unroll
        for (int j = 0; j < 16; j++) {
            float re = sre[j], im = sim_[j];
            float wre, wim;
            if (pc == 0)      { wre = re;   wim = im;  }
            else if (pc == 1) { wre = im;   wim = -re; }
            else if (pc == 2) { wre = -re;  wim = -im; }
            else              { wre = -im;  wim = re;  }
            shWre[j][col] = wre;
            shWim[j][col] = wim;
        }
    }
    __syncthreads();

    // A_w[x][y] = sum_j s_w(j)(Wre[j][x]Wre[j][y] + Wim[j][x]Wim[j][y])
    for (int idx = tid; idx < 1024; idx += blockDim.x) {
        const int w = idx >> 8;
        const int x = (idx >> 4) & 15;
        const int y = idx & 15;
        const int bitpos = 3 - w;
        float a = 0.f;
#pragma unroll
        for (int j = 0; j < 16; j++) {
            float sgn = ((j >> bitpos) & 1) ? -1.f : 1.f;
            a += sgn * (shWre[j][x] * shWre[j][y] + shWim[j][x] * shWim[j][y]);
        }
        sA[w][x][y] = a;
    }
    __syncthreads();

    // T_w[abcd] = (1/16) sum_x sgn(popc(x&m1)) A_w[x][x^m2]
    for (int idx = tid; idx < 324; idx += blockDim.x) {
        const int w = idx / 81;
        const int rem = idx % 81;
        const int a = rem / 27, b = (rem / 9) % 3, c = (rem / 3) % 3, d = rem % 3;
        int m1 = 0, m2 = 0;
        if (a == 1) m1 |= 8; else if (a == 2) m2 |= 8;
        if (b == 1) m1 |= 4; else if (b == 2) m2 |= 4;
        if (c == 1) m1 |= 2; else if (c == 2) m2 |= 2;
        if (d == 1) m1 |= 1; else if (d == 2) m2 |= 1;
        float sum = 0.f;
#pragma unroll
        for (int x = 0; x < 16; x++) {
            float sgn = (__popc(x & m1) & 1) ? -1.f : 1.f;
            sum += sgn * sA[w][x][x ^ m2];
        }
        sT[w][a * 3 + b][c * 3 + d] = sum * 0.0625f;
    }
    __syncthreads();

    // Extract the 24 structurally-nonzero entries (Pauli-propagation sparsity).
    if (tid < 8) {   // P0: a,b,d in {1,2}
        const int a = (tid >> 2) + 1, b = ((tid >> 1) & 1) + 1, d = (tid & 1) + 1;
        g_P[tid] = sT[0][a * 3 + b][d];
    } else if (tid < 16) {  // P1: a,c,d in {1,2}
        const int r = tid - 8;
        const int a = (r >> 2) + 1, c = ((r >> 1) & 1) + 1, d = (r & 1) + 1;
        g_P[tid] = sT[1][a * 3][c * 3 + d];
    } else if (tid < 20) {  // P2: b,d in {1,2}
        const int r = tid - 16;
        const int b = (r >> 1) + 1, d = (r & 1) + 1;
        g_P[tid] = sT[2][b][d];
    } else if (tid < 24) {  // P3: a,c in {1,2}
        const int r = tid - 20;
        const int a = (r >> 1) + 1, c = (r & 1) + 1;
        g_P[tid] = sT[3][a * 3][c * 3];
    }
}

// ---------------------------------------------------------------------------
// Main: one sample per thread, 24-coefficient sparse evaluation.
// out0 = f(x0,x1,x3); out1 = f(x0,x2,x3); out2 = f(x1,x3); out3 = f(x0,x2)
// ---------------------------------------------------------------------------
__global__ __launch_bounds__(256) void qenc_main_kernel(
    const float4* __restrict__ x4, float4* __restrict__ out4, int n)
{
    const int i = blockIdx.x * 256 + threadIdx.x;
    if (i >= n) return;

    const float4 xv = x4[i];
    float c0, s0, c1, s1, c2, s2, c3, s3;
    __sincosf(xv.x, &s0, &c0);
    __sincosf(xv.y, &s1, &c1);
    __sincosf(xv.z, &s2, &c2);
    __sincosf(xv.w, &s3, &c3);

    // out0: wires 0,1,3
    float a1 = fmaf(c_P[1], s3, c_P[0] * c3);
    float a2 = fmaf(c_P[3], s3, c_P[2] * c3);
    float a3 = fmaf(c_P[5], s3, c_P[4] * c3);
    float a4 = fmaf(c_P[7], s3, c_P[6] * c3);
    float u1 = fmaf(a2, s1, a1 * c1);
    float u2 = fmaf(a4, s1, a3 * c1);
    const float o0 = fmaf(u2, s0, u1 * c0);

    // out1: wires 0,2,3
    float b1 = fmaf(c_P[9],  s3, c_P[8]  * c3);
    float b2 = fmaf(c_P[11], s3, c_P[10] * c3);
    float b3 = fmaf(c_P[13], s3, c_P[12] * c3);
    float b4 = fmaf(c_P[15], s3, c_P[14] * c3);
    float v1 = fmaf(b2, s2, b1 * c2);
    float v2 = fmaf(b4, s2, b3 * c2);
    const float o1 = fmaf(v2, s0, v1 * c0);

    // out2: wires 1,3
    float d1 = fmaf(c_P[17], s3, c_P[16] * c3);
    float d2 = fmaf(c_P[19], s3, c_P[18] * c3);
    const float o2 = fmaf(d2, s1, d1 * c1);

    // out3: wires 0,2
    float e1 = fmaf(c_P[21], s2, c_P[20] * c2);
    float e2 = fmaf(c_P[23], s2, c_P[22] * c2);
    const float o3 = fmaf(e2, s0, e1 * c0);

    out4[i] = make_float4(o0, o1, o2, o3);
}

extern "C" void kernel_launch(void* const* d_in, const int* in_sizes, int n_in,
                              void* d_out, int out_size) {
    const float* x = (const float*)d_in[0];        // [B, 4] float32
    const float* weights = (const float*)d_in[1];  // [2, 4] float32
    float* out = (float*)d_out;                    // [B, 4] float32

    const int n = in_sizes[0] / 4;

    void* cdst = nullptr;
    void* gsrc = nullptr;
    cudaGetSymbolAddress(&cdst, c_P);
    cudaGetSymbolAddress(&gsrc, g_P);

    prep_kernel<<<1, 512>>>(weights);
    cudaMemcpyAsync(cdst, gsrc, sizeof(float) * 24, cudaMemcpyDeviceToDevice);
    qenc_main_kernel<<<(n + 255) / 256, 256>>>(
        (const float4*)x, (float4*)out, n);
}